// round 2
// baseline (speedup 1.0000x reference)
#include <cuda_runtime.h>
#include <cstdint>

#define BB 8
#define NN 262144
#define KK 256
#define DD 16
#define CAP 2048
#define MMAX 1024

// ---------------- scratch (device globals; no allocation) ----------------
__device__ float  g_sum_f [BB][KK];   // sum of focal over CP hits per segment
__device__ int    g_cnt_cp[BB][KK];   // CP count per segment (cp & valid)
__device__ int    g_inst  [BB][KK];   // instance size (valid points) per segment
__device__ int    g_first [BB][KK];   // first CP index per segment (init NN)
__device__ float  g_sd2   [BB][KK];   // sum of squared dist to anchor per segment
__device__ float4 g_anchor[BB][KK][4];// anchor embeddings (D=16 as 4x float4)
__device__ int    g_Mv    [BB];       // count of cp & valid per event
__device__ int    g_cplist[BB][CAP];  // collected cp&valid indices (unordered)
__device__ float  g_scal_f[BB][4];    // 0: sum ce0*~cp, 1: sum ce0*bg, 2: pos_margin num, 3: neg_margin num
__device__ int    g_scal_i[BB][4];    // 0: n_cp(all), 1: n_ncp, 2: n_bg, 3: n_valid
__device__ float  g_rep   [BB];       // repulsion term per event

// ---------------- init ----------------
__global__ void init_kernel() {
    int t = blockIdx.x * blockDim.x + threadIdx.x;   // 2048 threads
    if (t < BB * KK) {
        int b = t >> 8, k = t & 255;
        g_sum_f[b][k]  = 0.f;
        g_cnt_cp[b][k] = 0;
        g_inst[b][k]   = 0;
        g_first[b][k]  = NN;
        g_sd2[b][k]    = 0.f;
    }
    if (t < BB) {
        g_Mv[t]  = 0;
        g_rep[t] = 0.f;
        #pragma unroll
        for (int j = 0; j < 4; j++) { g_scal_f[t][j] = 0.f; g_scal_i[t][j] = 0; }
    }
}

// ---------------- pass A: beta/sid/cp scan ----------------
__global__ void __launch_bounds__(256) pass_a_kernel(
    const float* __restrict__ beta,
    const int* __restrict__ sid,
    const int* __restrict__ cp)
{
    const int b   = blockIdx.y;
    const int tid = threadIdx.x;

    __shared__ float s_f[KK];
    __shared__ int   s_cnt[KK];
    __shared__ int   s_inst[KK];
    __shared__ int   s_first[KK];
    __shared__ float s_sc[4];
    __shared__ int   s_si[4];

    for (int k = tid; k < KK; k += 256) { s_f[k] = 0.f; s_cnt[k] = 0; s_inst[k] = 0; s_first[k] = NN; }
    if (tid < 4) { s_sc[tid] = 0.f; s_si[tid] = 0; }
    __syncthreads();

    float ce0n = 0.f, bg = 0.f, pm = 0.f, nm = 0.f;
    int ncp = 0, nncp = 0, nbg = 0, nval = 0;

    const int blk_base = blockIdx.x * 4096;
    #pragma unroll 4
    for (int i = 0; i < 16; i++) {
        const int li = blk_base + i * 256 + tid;           // local index in event
        const size_t gi = (size_t)b * NN + li;
        const int s = sid[gi];
        const int c = cp[gi];
        const float x = beta[gi];

        const float p   = 1.f / (1.f + expf(-x));
        const float ce0 = fmaxf(x, 0.f) + log1pf(expf(-fabsf(x)));  // softplus(x)
        const float ce1 = ce0 - x;                                   // softplus(-x)
        const bool valid = (s >= 0);

        if (c) {
            ncp++;
            pm += fmaxf(0.8f - p, 0.f);       // THR + MARGIN = 0.8
            if (valid) {
                const float om = 1.f - p;
                const float focal = 0.75f * om * om * ce1;
                atomicAdd(&s_f[s], focal);
                atomicAdd(&s_cnt[s], 1);
                atomicMin(&s_first[s], li);
                int pos = atomicAdd(&g_Mv[b], 1);
                if (pos < CAP) g_cplist[b][pos] = li;
            }
        } else {
            nncp++;
            ce0n += ce0;
            nm += fmaxf(p - 0.2f, 0.f);       // THR - MARGIN = 0.2
        }
        if (s == -1) { nbg++; bg += ce0; }
        if (valid)   { nval++; atomicAdd(&s_inst[s], 1); }
    }

    atomicAdd(&s_sc[0], ce0n);
    atomicAdd(&s_sc[1], bg);
    atomicAdd(&s_sc[2], pm);
    atomicAdd(&s_sc[3], nm);
    atomicAdd(&s_si[0], ncp);
    atomicAdd(&s_si[1], nncp);
    atomicAdd(&s_si[2], nbg);
    atomicAdd(&s_si[3], nval);
    __syncthreads();

    for (int k = tid; k < KK; k += 256) {
        if (s_f[k] != 0.f)  atomicAdd(&g_sum_f[b][k], s_f[k]);
        if (s_cnt[k])       atomicAdd(&g_cnt_cp[b][k], s_cnt[k]);
        if (s_inst[k])      atomicAdd(&g_inst[b][k], s_inst[k]);
        if (s_first[k] < NN) atomicMin(&g_first[b][k], s_first[k]);
    }
    if (tid < 4) {
        atomicAdd(&g_scal_f[b][tid], s_sc[tid]);
        atomicAdd(&g_scal_i[b][tid], s_si[tid]);
    }
}

// ---------------- anchor gather ----------------
__global__ void gather_anchor_kernel(const float* __restrict__ embed) {
    int t = blockIdx.x * blockDim.x + threadIdx.x;   // BB*KK*4 = 8192 threads
    if (t >= BB * KK * 4) return;
    int q = t & 3;
    int k = (t >> 2) & (KK - 1);
    int b = t >> 10;
    int fi = g_first[b][k];
    float4 v = make_float4(0.f, 0.f, 0.f, 0.f);
    if (fi < NN)
        v = reinterpret_cast<const float4*>(embed + ((size_t)b * NN + fi) * DD)[q];
    g_anchor[b][k][q] = v;
}

// ---------------- pass B: attraction distances ----------------
__global__ void __launch_bounds__(256) pass_b_kernel(
    const float* __restrict__ embed,
    const int* __restrict__ sid)
{
    const int b   = blockIdx.y;
    const int tid = threadIdx.x;

    __shared__ float4        sA[KK][4];    // 16 KB anchors
    __shared__ float         sd2[KK];
    __shared__ unsigned char shc[KK];

    // load anchors (256*4 float4 = 1024 loads)
    for (int i = tid; i < KK * 4; i += 256)
        sA[i >> 2][i & 3] = g_anchor[b][i >> 2][i & 3];
    for (int k = tid; k < KK; k += 256) {
        sd2[k] = 0.f;
        shc[k] = (g_cnt_cp[b][k] > 0) ? 1 : 0;
    }
    __syncthreads();

    const int blk_base = blockIdx.x * 4096;
    for (int i = 0; i < 16; i++) {
        const int li = blk_base + i * 256 + tid;
        const size_t gi = (size_t)b * NN + li;
        const int s = sid[gi];
        if (s >= 0 && shc[s]) {
            const float4* e = reinterpret_cast<const float4*>(embed + gi * DD);
            float d2 = 0.f;
            #pragma unroll
            for (int q = 0; q < 4; q++) {
                float4 ev = e[q];
                float4 av = sA[s][q];
                float dx = ev.x - av.x, dy = ev.y - av.y;
                float dz = ev.z - av.z, dw = ev.w - av.w;
                d2 += dx * dx + dy * dy + dz * dz + dw * dw;
            }
            atomicAdd(&sd2[s], d2);
        }
    }
    __syncthreads();
    for (int k = tid; k < KK; k += 256)
        if (sd2[k] != 0.f) atomicAdd(&g_sd2[b][k], sd2[k]);
}

// ---------------- repulsion ----------------
__global__ void __launch_bounds__(1024) repulsion_kernel(const float* __restrict__ embed) {
    const int b   = blockIdx.x;
    const int tid = threadIdx.x;

    __shared__ int   sidx[CAP];           // 8 KB
    __shared__ float ej[256 * DD];        // 16 KB j-tile
    __shared__ float red[32];

    const int Mv   = g_Mv[b];
    const int mcol = min(Mv, CAP);
    for (int i = tid; i < CAP; i += 1024)
        sidx[i] = (i < mcol) ? g_cplist[b][i] : 0x7fffffff;
    __syncthreads();

    const int msel = min(Mv, MMAX);
    if (Mv > MMAX) {
        // bitonic sort CAP elements: select lowest MMAX indices
        for (int ksz = 2; ksz <= CAP; ksz <<= 1) {
            for (int j = ksz >> 1; j > 0; j >>= 1) {
                for (int i = tid; i < CAP; i += 1024) {
                    int ixj = i ^ j;
                    if (ixj > i) {
                        bool up = ((i & ksz) == 0);
                        int a = sidx[i], c = sidx[ixj];
                        if ((a > c) == up) { sidx[i] = c; sidx[ixj] = a; }
                    }
                }
                __syncthreads();
            }
        }
    }

    const bool act = (tid < msel);
    float myE[DD];
    if (act) {
        const float* e = embed + ((size_t)b * NN + sidx[tid]) * DD;
        #pragma unroll
        for (int d = 0; d < DD; d++) myE[d] = e[d];
    }

    float acc = 0.f;
    for (int j0 = 0; j0 < msel; j0 += 256) {
        const int cnt = min(256, msel - j0);
        __syncthreads();
        for (int i = tid; i < cnt * DD; i += 1024) {
            int jj = i >> 4, dd = i & 15;
            ej[i] = embed[((size_t)b * NN + sidx[j0 + jj]) * DD + dd];
        }
        __syncthreads();
        if (act) {
            for (int j = 0; j < cnt; j++) {
                float d2 = 0.f;
                #pragma unroll
                for (int d = 0; d < DD; d++) {
                    float df = myE[d] - ej[j * DD + d];
                    d2 += df * df;
                }
                acc += expf(-d2);
            }
        }
    }

    // block reduce
    #pragma unroll
    for (int off = 16; off; off >>= 1) acc += __shfl_down_sync(0xffffffff, acc, off);
    if ((tid & 31) == 0) red[tid >> 5] = acc;
    __syncthreads();
    if (tid == 0) {
        float tot = 0.f;
        for (int w = 0; w < 32; w++) tot += red[w];
        float fM = (float)Mv;
        g_rep[b] = (Mv > 1) ? tot / fmaxf(fM * fM, 1.f) : 0.f;   // REP_W = 1
    }
}

// ---------------- finalize ----------------
__global__ void __launch_bounds__(256) finalize_kernel(float* __restrict__ out) {
    const int tid  = threadIdx.x;
    const int lane = tid & 31;
    const int wid  = tid >> 5;
    __shared__ float rw[8], rwf[8], rat[8];
    __shared__ float s_total[1], s_cnt[1];
    if (tid == 0) { s_total[0] = 0.f; s_cnt[0] = 0.f; }
    __syncthreads();

    for (int b = 0; b < BB; b++) {
        const int   c    = g_cnt_cp[b][tid];
        const int   inst = g_inst[b][tid];
        float w = 0.f, wf = 0.f, at = 0.f;
        if (c > 0) {
            w  = (float)inst;
            wf = w * g_sum_f[b][tid] / fmaxf((float)c, 1.f);
            at = g_sd2[b][tid] / fmaxf((float)inst, 1.f);
        }
        #pragma unroll
        for (int off = 16; off; off >>= 1) {
            w  += __shfl_down_sync(0xffffffff, w,  off);
            wf += __shfl_down_sync(0xffffffff, wf, off);
            at += __shfl_down_sync(0xffffffff, at, off);
        }
        if (lane == 0) { rw[wid] = w; rwf[wid] = wf; rat[wid] = at; }
        __syncthreads();
        if (tid == 0) {
            float sw = 0.f, swf = 0.f, sat = 0.f;
            for (int q = 0; q < 8; q++) { sw += rw[q]; swf += rwf[q]; sat += rat[q]; }
            const float pos_bce = swf / fmaxf(sw, 1.f);

            const float n_cp  = (float)g_scal_i[b][0];
            const float n_ncp = (float)g_scal_i[b][1];
            const float n_bg  = (float)g_scal_i[b][2];
            const int   n_val = g_scal_i[b][3];

            const float neg_bce    = (n_ncp > 0.f) ? g_scal_f[b][0] / fmaxf(n_ncp, 1.f) : 0.f;
            const float bg_bce     = (n_bg  > 0.f) ? g_scal_f[b][1] / fmaxf(n_bg,  1.f) : 0.f;
            const float pos_margin = g_scal_f[b][2] / fmaxf(n_cp, 1.f);
            const float neg_margin = (n_ncp > 0.f) ? g_scal_f[b][3] / fmaxf(n_ncp, 1.f) : 0.f;

            const float beta_loss = 10.f * pos_bce + 3.f * neg_bce + 6.f * bg_bce
                                  + 10.f * (pos_margin + neg_margin);
            const float loss = beta_loss + sat /*ATTR_W=1*/ + g_rep[b];

            const bool ok = (n_val > 0) && (g_Mv[b] > 0);
            if (ok) { s_total[0] += loss; s_cnt[0] += 1.f; }
        }
        __syncthreads();
    }
    if (tid == 0)
        out[0] = (s_cnt[0] > 0.f) ? s_total[0] / fmaxf(s_cnt[0], 1.f) : 0.f;
}

// ---------------- launch ----------------
extern "C" void kernel_launch(void* const* d_in, const int* in_sizes, int n_in,
                              void* d_out, int out_size)
{
    (void)in_sizes; (void)n_in; (void)out_size;
    const float* beta  = (const float*)d_in[0];
    const float* embed = (const float*)d_in[1];
    const int*   sid   = (const int*)d_in[2];
    const int*   cp    = (const int*)d_in[3];

    init_kernel<<<8, 256>>>();
    pass_a_kernel<<<dim3(64, BB), 256>>>(beta, sid, cp);
    gather_anchor_kernel<<<32, 256>>>(embed);
    pass_b_kernel<<<dim3(64, BB), 256>>>(embed, sid);
    repulsion_kernel<<<BB, 1024>>>(embed);
    finalize_kernel<<<1, 256>>>((float*)d_out);
}